// round 2
// baseline (speedup 1.0000x reference)
#include <cuda_runtime.h>
#include <cuda_fp16.h>
#include <stdint.h>

#define MAXN    1048576        // >= 1,000,000 rows
#define KTAPS   27
#define CIN     32
#define COUT    32
#define MBLOCK  256
#define NTHREADS 256

// Scratch (allocation-free): fp16 copy of X with permuted channel pairs, fp16 W.
__device__ __align__(16) __half g_x16[(size_t)MAXN * CIN];            // 64 MiB
__device__ __align__(16) __half g_w16[KTAPS * COUT * CIN];            // [tap][n][k'] 54 KiB
__device__ int g_nbr_is64;                                            // neighbor dtype flag

// Involution on channel-pair index (s in 0..15): sigma(sigma(s)) == s
__device__ __forceinline__ int sigma(int s) { return ((s & 3) << 2) | (s >> 2); }

// ---------------- Neighbor dtype detection ----------------
// View nbr as int32 words. If the true dtype is int64 (nonneg values < 2^31,
// little-endian), every odd-position word is 0. If int32, odd words are random
// neighbor indices in [0, N) -> OR over a 2M-word sample is nonzero w.p. ~1.
// Sample region (2^22 words = 16 MB) is in-bounds under BOTH interpretations
// (int32 view has 27M words).
__global__ void detect_nbr_kernel(const int* __restrict__ words) {
    int nz = 0;
    for (int t = threadIdx.x * 2 + 1; t < (1 << 22); t += 2 * blockDim.x)
        nz |= words[t];
    int any = __syncthreads_or(nz != 0);
    if (threadIdx.x == 0) g_nbr_is64 = any ? 0 : 1;
}

// ---------------- X conversion: fp32 [N,32] -> fp16 permuted [N,32] ----------------
__global__ void convert_x_kernel(const float* __restrict__ x, int n) {
    long long tid = (long long)blockIdx.x * blockDim.x + threadIdx.x;
    long long total = (long long)n * 16;
    if (tid >= total) return;
    int i = (int)(tid >> 4);
    int s = (int)(tid & 15);
    int p = sigma(s);                          // memory slot s holds original pair sigma(s)
    float2 v = *(const float2*)(x + (size_t)i * CIN + 2 * p);
    ((__half2*)g_x16)[(size_t)i * 16 + s] = __floats2half2_rn(v.x, v.y);
}

// ---------------- W conversion: fp32 [tap][c][n] -> fp16 [tap][n][k'] ----------------
__global__ void convert_w_kernel(const float* __restrict__ w) {
    int e = blockIdx.x * blockDim.x + threadIdx.x;
    if (e >= KTAPS * COUT * CIN) return;
    int tap = e / (COUT * CIN);
    int rem = e % (COUT * CIN);
    int nn  = rem / CIN;
    int kp  = rem % CIN;                       // permuted k position
    int s   = kp >> 1, bit = kp & 1;
    int c   = 2 * sigma(s) + bit;              // original input channel
    g_w16[e] = __float2half_rn(w[(size_t)tap * CIN * COUT + (size_t)c * COUT + nn]);
}

// ---------------- fp16 MMA m16n8k16, fp32 accumulate ----------------
__device__ __forceinline__ void mma16816(float c[4],
                                         uint32_t a0, uint32_t a1, uint32_t a2, uint32_t a3,
                                         uint32_t b0, uint32_t b1) {
    asm("mma.sync.aligned.m16n8k16.row.col.f32.f16.f16.f32 "
        "{%0,%1,%2,%3}, {%4,%5,%6,%7}, {%8,%9}, {%0,%1,%2,%3};\n"
        : "+f"(c[0]), "+f"(c[1]), "+f"(c[2]), "+f"(c[3])
        : "r"(a0), "r"(a1), "r"(a2), "r"(a3), "r"(b0), "r"(b1));
}

// ---------------- Main: gather + 27-tap MMA accumulate ----------------
// smem: [0, 55296)  fp16 W (uint4 view, [tap][n][16 u32])
//       [55296, 82944) int32 neighbor indices [256 rows][27 taps]
#define SMEM_BYTES (55296 + MBLOCK * KTAPS * 4)

__global__ __launch_bounds__(NTHREADS, 2)
void conv_main_kernel(const void* __restrict__ nbr_raw,
                      const float* __restrict__ bias,
                      float* __restrict__ out, int n) {
    extern __shared__ uint8_t smem[];
    uint4* w_s4  = (uint4*)smem;
    int*   nbr_s = (int*)(smem + 55296);

    const int tid = threadIdx.x;
    const int i0  = blockIdx.x * MBLOCK;
    const int is64 = g_nbr_is64;

    // Stage W (3456 uint4, coalesced)
    const uint4* wg4 = (const uint4*)g_w16;
    #pragma unroll 4
    for (int t = tid; t < 3456; t += NTHREADS) w_s4[t] = wg4[t];

    // Stage neighbor indices (256*27 entries -> int32), coalesced, tail-guarded,
    // dtype-agnostic (uniform branch on detected flag).
    if (is64) {
        const long long* nbr = (const long long*)nbr_raw;
        for (int t = tid; t < MBLOCK * KTAPS; t += NTHREADS) {
            int r = t / KTAPS;
            long long v = (i0 + r < n) ? nbr[(size_t)i0 * KTAPS + t] : 0;
            nbr_s[t] = (int)v;
        }
    } else {
        const int* nbr = (const int*)nbr_raw;
        for (int t = tid; t < MBLOCK * KTAPS; t += NTHREADS) {
            int r = t / KTAPS;
            nbr_s[t] = (i0 + r < n) ? nbr[(size_t)i0 * KTAPS + t] : 0;
        }
    }
    __syncthreads();

    const int lane = tid & 31;
    const int warp = tid >> 5;
    const int q    = lane & 3;     // quad column
    const int nrow = lane >> 2;    // 0..7
    const int mb   = warp * 32;    // warp's 32 rows within block

    // Bias fragment: column t*8 + 2q (+1)
    float2 bz[4];
    #pragma unroll
    for (int t = 0; t < 4; t++)
        bz[t] = *(const float2*)(bias + t * 8 + 2 * q);

    float acc[2][4][4];
    #pragma unroll
    for (int mt = 0; mt < 2; mt++)
        #pragma unroll
        for (int t = 0; t < 4; t++)
            #pragma unroll
            for (int j = 0; j < 4; j++) acc[mt][t][j] = 0.f;

    const uint4* x4 = (const uint4*)g_x16;     // row i at uint4 offset i*4

    // Prologue: fetch A for tap 0 (one LDG.128 per row-half per m-tile)
    uint4 aC[4];
    #pragma unroll
    for (int mt = 0; mt < 2; mt++) {
        int rlo = mb + mt * 16 + nrow;
        int ilo = nbr_s[rlo * KTAPS + 0];
        int ihi = nbr_s[(rlo + 8) * KTAPS + 0];
        aC[mt * 2 + 0] = x4[(size_t)ilo * 4 + q];
        aC[mt * 2 + 1] = x4[(size_t)ihi * 4 + q];
    }

    for (int k = 0; k < KTAPS; k++) {
        // Prefetch next tap's A while MMAs run on current
        uint4 aN[4];
        const bool more = (k + 1 < KTAPS);
        if (more) {
            #pragma unroll
            for (int mt = 0; mt < 2; mt++) {
                int rlo = mb + mt * 16 + nrow;
                int ilo = nbr_s[rlo * KTAPS + (k + 1)];
                int ihi = nbr_s[(rlo + 8) * KTAPS + (k + 1)];
                aN[mt * 2 + 0] = x4[(size_t)ilo * 4 + q];
                aN[mt * 2 + 1] = x4[(size_t)ihi * 4 + q];
            }
        }

        #pragma unroll
        for (int t = 0; t < 4; t++) {
            // B fragments for both k-chunks of n-tile t: one LDS.128
            uint4 bw = w_s4[k * 128 + (t * 8 + nrow) * 4 + q];
            #pragma unroll
            for (int mt = 0; mt < 2; mt++) {
                const uint4& lo = aC[mt * 2 + 0];
                const uint4& hi = aC[mt * 2 + 1];
                mma16816(acc[mt][t], lo.x, hi.x, lo.y, hi.y, bw.x, bw.y); // k 0..15
                mma16816(acc[mt][t], lo.z, hi.z, lo.w, hi.w, bw.z, bw.w); // k 16..31
            }
        }

        if (more) {
            #pragma unroll
            for (int j = 0; j < 4; j++) aC[j] = aN[j];
        }
    }

    // Epilogue: add bias, store float2 per (m-tile, row-half, n-tile)
    #pragma unroll
    for (int mt = 0; mt < 2; mt++) {
        int rbase = i0 + mb + mt * 16 + nrow;
        #pragma unroll
        for (int half = 0; half < 2; half++) {
            int r = rbase + half * 8;
            if (r < n) {
                float* po = out + (size_t)r * COUT + 2 * q;
                #pragma unroll
                for (int t = 0; t < 4; t++) {
                    float2 v;
                    v.x = acc[mt][t][half * 2 + 0] + bz[t].x;
                    v.y = acc[mt][t][half * 2 + 1] + bz[t].y;
                    *(float2*)(po + t * 8) = v;
                }
            }
        }
    }
}

// ---------------- Launch ----------------
extern "C" void kernel_launch(void* const* d_in, const int* in_sizes, int n_in,
                              void* d_out, int out_size) {
    const float* x    = (const float*)d_in[0];       // [N, 32] f32
    const float* w    = (const float*)d_in[1];       // [27, 32, 32] f32
    const float* bias = (const float*)d_in[2];       // [32] f32
    const void*  nbr  = d_in[3];                     // [N, 27] int32 OR int64 (detected)
    float*       out  = (float*)d_out;               // [N, 32] f32

    const int n = in_sizes[0] / CIN;

    cudaFuncSetAttribute(conv_main_kernel,
                         cudaFuncAttributeMaxDynamicSharedMemorySize, SMEM_BYTES);

    detect_nbr_kernel<<<1, 256>>>((const int*)nbr);
    {
        long long total = (long long)n * 16;
        int blocks = (int)((total + NTHREADS - 1) / NTHREADS);
        convert_x_kernel<<<blocks, NTHREADS>>>(x, n);
    }
    {
        int total = KTAPS * COUT * CIN;
        convert_w_kernel<<<(total + NTHREADS - 1) / NTHREADS, NTHREADS>>>(w);
    }
    {
        int blocks = (n + MBLOCK - 1) / MBLOCK;
        conv_main_kernel<<<blocks, NTHREADS, SMEM_BYTES>>>(nbr, bias, out, n);
    }
}

// round 3
// speedup vs baseline: 1.5666x; 1.5666x over previous
#include <cuda_runtime.h>
#include <cuda_fp16.h>
#include <stdint.h>

#define MAXN    1048576        // >= 1,000,000 rows
#define KTAPS   27
#define CIN     32
#define COUT    32
#define MBLOCK  128            // rows per block (1 m16-tile x 16 rows per warp)
#define NTHREADS 256

// Scratch (allocation-free): fp16 copy of X with permuted channel pairs, fp16 W.
__device__ __align__(16) __half g_x16[(size_t)MAXN * CIN];            // 64 MiB
__device__ __align__(16) __half g_w16[KTAPS * COUT * CIN];            // [tap][n][k'] 54 KiB
__device__ int g_nbr_is64;                                            // neighbor dtype flag

// Involution on channel-pair index (s in 0..15): sigma(sigma(s)) == s
__device__ __forceinline__ int sigma(int s) { return ((s & 3) << 2) | (s >> 2); }

// ---------------- Neighbor dtype detection (tiny sample) ----------------
// View nbr as int32 words. int64 (values < 2^31, LE) -> all odd words are 0.
// int32 -> odd words are uniform in [0, N); P(2048 samples all zero) ~ 1e-12288.
__global__ void detect_nbr_kernel(const int* __restrict__ words) {
    int nz = 0;
    #pragma unroll
    for (int j = 0; j < 8; j++)
        nz |= words[2 * (threadIdx.x * 8 + j) + 1];
    int any = __syncthreads_or(nz != 0);
    if (threadIdx.x == 0) g_nbr_is64 = any ? 0 : 1;
}

// ---------------- X conversion: fp32 [N,32] -> fp16 permuted [N,32] ----------------
__global__ void convert_x_kernel(const float* __restrict__ x, int n) {
    long long tid = (long long)blockIdx.x * blockDim.x + threadIdx.x;
    long long total = (long long)n * 16;
    if (tid >= total) return;
    int i = (int)(tid >> 4);
    int s = (int)(tid & 15);
    int p = sigma(s);                          // memory slot s holds original pair sigma(s)
    float2 v = *(const float2*)(x + (size_t)i * CIN + 2 * p);
    ((__half2*)g_x16)[(size_t)i * 16 + s] = __floats2half2_rn(v.x, v.y);
}

// ---------------- W conversion: fp32 [tap][c][n] -> fp16 [tap][n][k'] ----------------
__global__ void convert_w_kernel(const float* __restrict__ w) {
    int e = blockIdx.x * blockDim.x + threadIdx.x;
    if (e >= KTAPS * COUT * CIN) return;
    int tap = e / (COUT * CIN);
    int rem = e % (COUT * CIN);
    int nn  = rem / CIN;
    int kp  = rem % CIN;                       // permuted k position
    int s   = kp >> 1, bit = kp & 1;
    int c   = 2 * sigma(s) + bit;              // original input channel
    g_w16[e] = __float2half_rn(w[(size_t)tap * CIN * COUT + (size_t)c * COUT + nn]);
}

// ---------------- fp16 MMA m16n8k16, fp32 accumulate ----------------
__device__ __forceinline__ void mma16816(float c[4],
                                         uint32_t a0, uint32_t a1, uint32_t a2, uint32_t a3,
                                         uint32_t b0, uint32_t b1) {
    asm("mma.sync.aligned.m16n8k16.row.col.f32.f16.f16.f32 "
        "{%0,%1,%2,%3}, {%4,%5,%6,%7}, {%8,%9}, {%0,%1,%2,%3};\n"
        : "+f"(c[0]), "+f"(c[1]), "+f"(c[2]), "+f"(c[3])
        : "r"(a0), "r"(a1), "r"(a2), "r"(a3), "r"(b0), "r"(b1));
}

// ---------------- Main: gather + 27-tap MMA accumulate ----------------
// smem: [0, 55296)          fp16 W (uint4 view, [tap][n-tile-row][16B])
//       [55296, 69120)      int32 neighbor indices [128 rows][27 taps]
#define W_SMEM   55296
#define SMEM_BYTES (W_SMEM + MBLOCK * KTAPS * 4)

__global__ __launch_bounds__(NTHREADS, 3)
void conv_main_kernel(const void* __restrict__ nbr_raw,
                      const float* __restrict__ bias,
                      float* __restrict__ out, int n) {
    extern __shared__ uint8_t smem[];
    uint4* w_s4  = (uint4*)smem;
    int*   nbr_s = (int*)(smem + W_SMEM);

    const int tid = threadIdx.x;
    const int i0  = blockIdx.x * MBLOCK;
    const int is64 = g_nbr_is64;

    // Stage W (3456 uint4, coalesced)
    const uint4* wg4 = (const uint4*)g_w16;
    #pragma unroll 4
    for (int t = tid; t < 3456; t += NTHREADS) w_s4[t] = wg4[t];

    // Stage neighbor indices (128*27 entries -> int32), coalesced, tail-guarded.
    if (is64) {
        const long long* nbr = (const long long*)nbr_raw;
        for (int t = tid; t < MBLOCK * KTAPS; t += NTHREADS) {
            int r = t / KTAPS;
            long long v = (i0 + r < n) ? nbr[(size_t)i0 * KTAPS + t] : 0;
            nbr_s[t] = (int)v;
        }
    } else {
        const int* nbr = (const int*)nbr_raw;
        for (int t = tid; t < MBLOCK * KTAPS; t += NTHREADS) {
            int r = t / KTAPS;
            nbr_s[t] = (i0 + r < n) ? nbr[(size_t)i0 * KTAPS + t] : 0;
        }
    }
    __syncthreads();

    const int lane = tid & 31;
    const int warp = tid >> 5;
    const int q    = lane & 3;     // quad column
    const int nrow = lane >> 2;    // 0..7
    const int rlo  = warp * 16 + nrow;   // warp's 16 rows: rlo, rlo+8

    // Acc init = bias (c0,c1 -> row nrow cols 2q,2q+1; c2,c3 -> row nrow+8 same cols)
    float acc[4][4];
    #pragma unroll
    for (int t = 0; t < 4; t++) {
        float2 b2 = *(const float2*)(bias + t * 8 + 2 * q);
        acc[t][0] = b2.x; acc[t][1] = b2.y;
        acc[t][2] = b2.x; acc[t][3] = b2.y;
    }

    const uint4* x4 = (const uint4*)g_x16;     // row i at uint4 offset i*4

    // Prologue: fetch A for tap 0 (one LDG.128 per row-half)
    uint4 aLo = x4[(size_t)nbr_s[rlo * KTAPS + 0] * 4 + q];
    uint4 aHi = x4[(size_t)nbr_s[(rlo + 8) * KTAPS + 0] * 4 + q];

    for (int k = 0; k < KTAPS; k++) {
        // Prefetch next tap's A while MMAs run on current
        uint4 nLo, nHi;
        const bool more = (k + 1 < KTAPS);
        if (more) {
            nLo = x4[(size_t)nbr_s[rlo * KTAPS + (k + 1)] * 4 + q];
            nHi = x4[(size_t)nbr_s[(rlo + 8) * KTAPS + (k + 1)] * 4 + q];
        }

        #pragma unroll
        for (int t = 0; t < 4; t++) {
            uint4 bw = w_s4[k * 128 + (t * 8 + nrow) * 4 + q];  // both k-chunks, one LDS.128
            mma16816(acc[t], aLo.x, aHi.x, aLo.y, aHi.y, bw.x, bw.y); // k 0..15
            mma16816(acc[t], aLo.z, aHi.z, aLo.w, aHi.w, bw.z, bw.w); // k 16..31
        }

        if (more) { aLo = nLo; aHi = nHi; }
    }

    // Epilogue: store float2 per (row-half, n-tile); bias already in acc
    #pragma unroll
    for (int half = 0; half < 2; half++) {
        int r = i0 + rlo + half * 8;
        if (r < n) {
            float* po = out + (size_t)r * COUT + 2 * q;
            #pragma unroll
            for (int t = 0; t < 4; t++) {
                float2 v;
                v.x = acc[t][half * 2 + 0];
                v.y = acc[t][half * 2 + 1];
                *(float2*)(po + t * 8) = v;
            }
        }
    }
}

// ---------------- Launch ----------------
extern "C" void kernel_launch(void* const* d_in, const int* in_sizes, int n_in,
                              void* d_out, int out_size) {
    const float* x    = (const float*)d_in[0];       // [N, 32] f32
    const float* w    = (const float*)d_in[1];       // [27, 32, 32] f32
    const float* bias = (const float*)d_in[2];       // [32] f32
    const void*  nbr  = d_in[3];                     // [N, 27] int32 OR int64 (detected)
    float*       out  = (float*)d_out;               // [N, 32] f32

    const int n = in_sizes[0] / CIN;

    cudaFuncSetAttribute(conv_main_kernel,
                         cudaFuncAttributeMaxDynamicSharedMemorySize, SMEM_BYTES);

    detect_nbr_kernel<<<1, 256>>>((const int*)nbr);
    {
        long long total = (long long)n * 16;
        int blocks = (int)((total + NTHREADS - 1) / NTHREADS);
        convert_x_kernel<<<blocks, NTHREADS>>>(x, n);
    }
    {
        int total = KTAPS * COUT * CIN;
        convert_w_kernel<<<(total + NTHREADS - 1) / NTHREADS, NTHREADS>>>(w);
    }
    {
        int blocks = (n + MBLOCK - 1) / MBLOCK;
        conv_main_kernel<<<blocks, NTHREADS, SMEM_BYTES>>>(nbr, bias, out, n);
    }
}

// round 4
// speedup vs baseline: 2.8448x; 1.8160x over previous
#include <cuda_runtime.h>
#include <cuda_fp16.h>
#include <stdint.h>

#define MAXN    1048576        // >= 1,000,000 rows
#define KTAPS   27
#define CIN     32
#define COUT    32
#define MBLOCK  256            // rows per block (2 m16-tiles x 16 rows per warp)
#define NTHREADS 256

// Scratch (allocation-free): fp16 copy of X with permuted channel pairs, fp16 W.
__device__ __align__(16) __half g_x16[(size_t)MAXN * CIN];            // 64 MiB
__device__ __align__(16) __half g_w16[KTAPS * COUT * CIN];            // [tap][n][k'] 54 KiB
__device__ int g_nbr_is64;                                            // neighbor dtype flag

// Involution on channel-pair index (s in 0..15): sigma(sigma(s)) == s
__device__ __forceinline__ int sigma(int s) { return ((s & 3) << 2) | (s >> 2); }

// ---------------- Neighbor dtype detection (tiny sample) ----------------
// View nbr as int32 words. int64 (values < 2^31, LE) -> all odd words are 0.
// int32 -> odd words are uniform in [0, N); P(2048 samples all zero) ~ 0.
__global__ void detect_nbr_kernel(const int* __restrict__ words) {
    int nz = 0;
    #pragma unroll
    for (int j = 0; j < 8; j++)
        nz |= words[2 * (threadIdx.x * 8 + j) + 1];
    int any = __syncthreads_or(nz != 0);
    if (threadIdx.x == 0) g_nbr_is64 = any ? 0 : 1;
}

// ---------------- X conversion: fp32 [N,32] -> fp16 permuted [N,32] ----------------
__global__ void convert_x_kernel(const float* __restrict__ x, int n) {
    long long tid = (long long)blockIdx.x * blockDim.x + threadIdx.x;
    long long total = (long long)n * 16;
    if (tid >= total) return;
    int i = (int)(tid >> 4);
    int s = (int)(tid & 15);
    int p = sigma(s);                          // memory slot s holds original pair sigma(s)
    float2 v = __ldcs((const float2*)(x + (size_t)i * CIN + 2 * p));
    ((__half2*)g_x16)[(size_t)i * 16 + s] = __floats2half2_rn(v.x, v.y);
}

// ---------------- W conversion: fp32 [tap][c][n] -> fp16 [tap][n][k'] ----------------
__global__ void convert_w_kernel(const float* __restrict__ w) {
    int e = blockIdx.x * blockDim.x + threadIdx.x;
    if (e >= KTAPS * COUT * CIN) return;
    int tap = e / (COUT * CIN);
    int rem = e % (COUT * CIN);
    int nn  = rem / CIN;
    int kp  = rem % CIN;                       // permuted k position
    int s   = kp >> 1, bit = kp & 1;
    int c   = 2 * sigma(s) + bit;              // original input channel
    g_w16[e] = __float2half_rn(w[(size_t)tap * CIN * COUT + (size_t)c * COUT + nn]);
}

// ---------------- fp16 MMA m16n8k16, fp32 accumulate ----------------
__device__ __forceinline__ void mma16816(float c[4],
                                         uint32_t a0, uint32_t a1, uint32_t a2, uint32_t a3,
                                         uint32_t b0, uint32_t b1) {
    asm("mma.sync.aligned.m16n8k16.row.col.f32.f16.f16.f32 "
        "{%0,%1,%2,%3}, {%4,%5,%6,%7}, {%8,%9}, {%0,%1,%2,%3};\n"
        : "+f"(c[0]), "+f"(c[1]), "+f"(c[2]), "+f"(c[3])
        : "r"(a0), "r"(a1), "r"(a2), "r"(a3), "r"(b0), "r"(b1));
}

// ---------------- Main: gather + 27-tap MMA, depth-2 pipelined ----------------
// smem: [0, 55296)          fp16 W (uint4 view, [tap][n-tile-row][16B])
//       [55296, 82944)      int32 neighbor indices [256 rows][27 taps]
#define W_SMEM     55296
#define SMEM_BYTES (W_SMEM + MBLOCK * KTAPS * 4)

__global__ __launch_bounds__(NTHREADS, 2)
void conv_main_kernel(const void* __restrict__ nbr_raw,
                      const float* __restrict__ bias,
                      float* __restrict__ out, int n) {
    extern __shared__ uint8_t smem[];
    uint4* w_s4  = (uint4*)smem;
    int*   nbr_s = (int*)(smem + W_SMEM);

    const int tid = threadIdx.x;
    const int i0  = blockIdx.x * MBLOCK;
    const int is64 = g_nbr_is64;

    // Stage W (3456 uint4, coalesced)
    const uint4* wg4 = (const uint4*)g_w16;
    #pragma unroll 4
    for (int t = tid; t < 3456; t += NTHREADS) w_s4[t] = wg4[t];

    // Stage neighbor indices (256*27 entries -> int32), coalesced, streaming hint.
    if (is64) {
        const long long* nbr = (const long long*)nbr_raw;
        for (int t = tid; t < MBLOCK * KTAPS; t += NTHREADS) {
            int r = t / KTAPS;
            long long v = (i0 + r < n) ? __ldcs(nbr + (size_t)i0 * KTAPS + t) : 0;
            nbr_s[t] = (int)v;
        }
    } else {
        const int* nbr = (const int*)nbr_raw;
        for (int t = tid; t < MBLOCK * KTAPS; t += NTHREADS) {
            int r = t / KTAPS;
            nbr_s[t] = (i0 + r < n) ? __ldcs(nbr + (size_t)i0 * KTAPS + t) : 0;
        }
    }
    __syncthreads();

    const int lane = tid & 31;
    const int warp = tid >> 5;
    const int q    = lane & 3;     // quad column (16B chunk within row)
    const int nrow = lane >> 2;    // 0..7
    const int mb   = warp * 32;    // warp's 32 rows within block

    // Acc init = bias
    float acc[2][4][4];
    #pragma unroll
    for (int t = 0; t < 4; t++) {
        float2 b2 = *(const float2*)(bias + t * 8 + 2 * q);
        #pragma unroll
        for (int mt = 0; mt < 2; mt++) {
            acc[mt][t][0] = b2.x; acc[mt][t][1] = b2.y;
            acc[mt][t][2] = b2.x; acc[mt][t][3] = b2.y;
        }
    }

    const uint4* x4 = (const uint4*)g_x16;     // row i at uint4 offset i*4

    // A gather for one tap into buffer (4 x LDG.128 per warp)
    #define LOAD_TAP(buf, k) do {                                           \
        _Pragma("unroll")                                                   \
        for (int mt = 0; mt < 2; mt++) {                                    \
            int rlo = mb + mt * 16 + nrow;                                  \
            int ilo = nbr_s[rlo * KTAPS + (k)];                             \
            int ihi = nbr_s[(rlo + 8) * KTAPS + (k)];                       \
            (buf)[mt * 2 + 0] = x4[(size_t)ilo * 4 + q];                    \
            (buf)[mt * 2 + 1] = x4[(size_t)ihi * 4 + q];                    \
        }                                                                   \
    } while (0)

    #define MMA_TAP(buf, k) do {                                            \
        _Pragma("unroll")                                                   \
        for (int t = 0; t < 4; t++) {                                       \
            uint4 bw = w_s4[(k) * 128 + (t * 8 + nrow) * 4 + q];            \
            _Pragma("unroll")                                               \
            for (int mt = 0; mt < 2; mt++) {                                \
                const uint4& lo = (buf)[mt * 2 + 0];                        \
                const uint4& hi = (buf)[mt * 2 + 1];                        \
                mma16816(acc[mt][t], lo.x, hi.x, lo.y, hi.y, bw.x, bw.y);   \
                mma16816(acc[mt][t], lo.z, hi.z, lo.w, hi.w, bw.z, bw.w);   \
            }                                                               \
        }                                                                   \
    } while (0)

    // Depth-2 software pipeline, 3 rotating register buffers, KTAPS = 9*3.
    uint4 A0[4], A1[4], A2[4];
    LOAD_TAP(A0, 0);
    LOAD_TAP(A1, 1);

    #pragma unroll 1
    for (int kk = 0; kk < KTAPS / 3; kk++) {
        int k = kk * 3;
        if (k + 2 < KTAPS) LOAD_TAP(A2, k + 2);
        MMA_TAP(A0, k);
        if (k + 3 < KTAPS) LOAD_TAP(A0, k + 3);
        MMA_TAP(A1, k + 1);
        if (k + 4 < KTAPS) LOAD_TAP(A1, k + 4);
        MMA_TAP(A2, k + 2);
    }

    // Epilogue: streaming stores (bias already in acc)
    #pragma unroll
    for (int mt = 0; mt < 2; mt++) {
        #pragma unroll
        for (int half = 0; half < 2; half++) {
            int r = i0 + mb + mt * 16 + nrow + half * 8;
            if (r < n) {
                float* po = out + (size_t)r * COUT + 2 * q;
                #pragma unroll
                for (int t = 0; t < 4; t++) {
                    float2 v;
                    v.x = acc[mt][t][half * 2 + 0];
                    v.y = acc[mt][t][half * 2 + 1];
                    __stcs((float2*)(po + t * 8), v);
                }
            }
        }
    }
}

// ---------------- Launch ----------------
extern "C" void kernel_launch(void* const* d_in, const int* in_sizes, int n_in,
                              void* d_out, int out_size) {
    const float* x    = (const float*)d_in[0];       // [N, 32] f32
    const float* w    = (const float*)d_in[1];       // [27, 32, 32] f32
    const float* bias = (const float*)d_in[2];       // [32] f32
    const void*  nbr  = d_in[3];                     // [N, 27] int32 OR int64 (detected)
    float*       out  = (float*)d_out;               // [N, 32] f32

    const int n = in_sizes[0] / CIN;

    cudaFuncSetAttribute(conv_main_kernel,
                         cudaFuncAttributeMaxDynamicSharedMemorySize, SMEM_BYTES);

    detect_nbr_kernel<<<1, 256>>>((const int*)nbr);
    {
        long long total = (long long)n * 16;
        int blocks = (int)((total + NTHREADS - 1) / NTHREADS);
        convert_x_kernel<<<blocks, NTHREADS>>>(x, n);
    }
    {
        int total = KTAPS * COUT * CIN;
        convert_w_kernel<<<(total + NTHREADS - 1) / NTHREADS, NTHREADS>>>(w);
    }
    {
        int blocks = (n + MBLOCK - 1) / MBLOCK;
        conv_main_kernel<<<blocks, NTHREADS, SMEM_BYTES>>>(nbr, bias, out, n);
    }
}

// round 5
// speedup vs baseline: 3.2632x; 1.1471x over previous
#include <cuda_runtime.h>
#include <cuda_fp16.h>
#include <stdint.h>

#define MAXN    1048576        // >= 1,000,000 rows
#define KTAPS   27
#define CIN     32
#define COUT    32
#define MBLOCK  256            // rows per tile (2 m16-tiles x 16 rows per warp)
#define NTHREADS 256

// Scratch (allocation-free): fp16 copy of X with permuted channel pairs, fp16 W.
__device__ __align__(16) __half g_x16[(size_t)MAXN * CIN];            // 64 MiB
__device__ __align__(16) __half g_w16[KTAPS * COUT * CIN];            // [tap][n][k'] 54 KiB
__device__ int g_nbr_is64;                                            // neighbor dtype flag

// Involution on channel-pair index (s in 0..15): sigma(sigma(s)) == s
__device__ __forceinline__ int sigma(int s) { return ((s & 3) << 2) | (s >> 2); }

// ---------------- Neighbor dtype detection (tiny sample) ----------------
__global__ void detect_nbr_kernel(const int* __restrict__ words) {
    int nz = 0;
    #pragma unroll
    for (int j = 0; j < 8; j++)
        nz |= words[2 * (threadIdx.x * 8 + j) + 1];
    int any = __syncthreads_or(nz != 0);
    if (threadIdx.x == 0) g_nbr_is64 = any ? 0 : 1;
}

// ---------------- X conversion: fp32 [N,32] -> fp16 permuted [N,32] ----------------
__global__ void convert_x_kernel(const float* __restrict__ x, int n) {
    long long tid = (long long)blockIdx.x * blockDim.x + threadIdx.x;
    long long total = (long long)n * 16;
    if (tid >= total) return;
    int i = (int)(tid >> 4);
    int s = (int)(tid & 15);
    int p = sigma(s);                          // memory slot s holds original pair sigma(s)
    float2 v = __ldcs((const float2*)(x + (size_t)i * CIN + 2 * p));
    ((__half2*)g_x16)[(size_t)i * 16 + s] = __floats2half2_rn(v.x, v.y);
}

// ---------------- W conversion: fp32 [tap][c][n] -> fp16 [tap][n][k'] ----------------
__global__ void convert_w_kernel(const float* __restrict__ w) {
    int e = blockIdx.x * blockDim.x + threadIdx.x;
    if (e >= KTAPS * COUT * CIN) return;
    int tap = e / (COUT * CIN);
    int rem = e % (COUT * CIN);
    int nn  = rem / CIN;
    int kp  = rem % CIN;                       // permuted k position
    int s   = kp >> 1, bit = kp & 1;
    int c   = 2 * sigma(s) + bit;              // original input channel
    g_w16[e] = __float2half_rn(w[(size_t)tap * CIN * COUT + (size_t)c * COUT + nn]);
}

// ---------------- fp16 MMA m16n8k16, fp32 accumulate ----------------
__device__ __forceinline__ void mma16816(float c[4],
                                         uint32_t a0, uint32_t a1, uint32_t a2, uint32_t a3,
                                         uint32_t b0, uint32_t b1) {
    asm("mma.sync.aligned.m16n8k16.row.col.f32.f16.f16.f32 "
        "{%0,%1,%2,%3}, {%4,%5,%6,%7}, {%8,%9}, {%0,%1,%2,%3};\n"
        : "+f"(c[0]), "+f"(c[1]), "+f"(c[2]), "+f"(c[3])
        : "r"(a0), "r"(a1), "r"(a2), "r"(a3), "r"(b0), "r"(b1));
}

// ---------------- Main: persistent blocks, gather + 27-tap MMA, depth-2 pipeline ----
// smem: [0, 55296)          fp16 W (uint4 view, [tap][n-tile-row][16B])
//       [55296, 82944)      int32 neighbor BYTE OFFSETS (idx*64) [256 rows][27 taps]
#define W_SMEM     55296
#define SMEM_BYTES (W_SMEM + MBLOCK * KTAPS * 4)

__global__ __launch_bounds__(NTHREADS, 2)
void conv_main_kernel(const void* __restrict__ nbr_raw,
                      const float* __restrict__ bias,
                      float* __restrict__ out, int n, int ntiles) {
    extern __shared__ uint8_t smem[];
    uint4* w_s4  = (uint4*)smem;
    int*   nbr_s = (int*)(smem + W_SMEM);

    const int tid  = threadIdx.x;
    const int is64 = g_nbr_is64;

    // Stage W once per persistent block (3456 uint4, coalesced)
    const uint4* wg4 = (const uint4*)g_w16;
    #pragma unroll 4
    for (int t = tid; t < 3456; t += NTHREADS) w_s4[t] = wg4[t];

    const int lane = tid & 31;
    const int warp = tid >> 5;
    const int q    = lane & 3;     // quad column (16B chunk within row)
    const int nrow = lane >> 2;    // 0..7
    const int mb   = warp * 32;    // warp's 32 rows within tile

    // Bias fragment (kept in regs across tiles)
    float2 bz[4];
    #pragma unroll
    for (int t = 0; t < 4; t++)
        bz[t] = *(const float2*)(bias + t * 8 + 2 * q);

    const char* xb = (const char*)g_x16 + q * 16;   // this thread's chunk base

    #define LOAD_TAP(buf, k) do {                                           \
        _Pragma("unroll")                                                   \
        for (int mt = 0; mt < 2; mt++) {                                    \
            int rlo = mb + mt * 16 + nrow;                                  \
            int olo = nbr_s[rlo * KTAPS + (k)];                             \
            int ohi = nbr_s[(rlo + 8) * KTAPS + (k)];                       \
            (buf)[mt * 2 + 0] = *(const uint4*)(xb + olo);                  \
            (buf)[mt * 2 + 1] = *(const uint4*)(xb + ohi);                  \
        }                                                                   \
    } while (0)

    #define MMA_TAP(buf, k) do {                                            \
        _Pragma("unroll")                                                   \
        for (int t = 0; t < 4; t++) {                                       \
            uint4 bw = w_s4[(k) * 128 + (t * 8 + nrow) * 4 + q];            \
            _Pragma("unroll")                                               \
            for (int mt = 0; mt < 2; mt++) {                                \
                const uint4& lo = (buf)[mt * 2 + 0];                        \
                const uint4& hi = (buf)[mt * 2 + 1];                        \
                mma16816(acc[mt][t], lo.x, hi.x, lo.y, hi.y, bw.x, bw.y);   \
                mma16816(acc[mt][t], lo.z, hi.z, lo.w, hi.w, bw.z, bw.w);   \
            }                                                               \
        }                                                                   \
    } while (0)

    for (int tile = blockIdx.x; tile < ntiles; tile += gridDim.x) {
        const int i0 = tile * MBLOCK;

        __syncthreads();   // previous tile's readers done before nbr_s overwrite
        // Stage neighbor byte-offsets (idx*64), coalesced, tail-guarded.
        if (is64) {
            const long long* nbr = (const long long*)nbr_raw;
            for (int t = tid; t < MBLOCK * KTAPS; t += NTHREADS) {
                int r = t / KTAPS;
                long long v = (i0 + r < n) ? __ldcs(nbr + (size_t)i0 * KTAPS + t) : 0;
                nbr_s[t] = ((int)v) << 6;
            }
        } else {
            const int* nbr = (const int*)nbr_raw;
            for (int t = tid; t < MBLOCK * KTAPS; t += NTHREADS) {
                int r = t / KTAPS;
                int v = (i0 + r < n) ? __ldcs(nbr + (size_t)i0 * KTAPS + t) : 0;
                nbr_s[t] = v << 6;
            }
        }
        __syncthreads();

        // Acc init = bias
        float acc[2][4][4];
        #pragma unroll
        for (int t = 0; t < 4; t++) {
            #pragma unroll
            for (int mt = 0; mt < 2; mt++) {
                acc[mt][t][0] = bz[t].x; acc[mt][t][1] = bz[t].y;
                acc[mt][t][2] = bz[t].x; acc[mt][t][3] = bz[t].y;
            }
        }

        // Depth-2 software pipeline, 3 rotating register buffers, KTAPS = 9*3.
        uint4 A0[4], A1[4], A2[4];
        LOAD_TAP(A0, 0);
        LOAD_TAP(A1, 1);

        #pragma unroll 1
        for (int kk = 0; kk < KTAPS / 3; kk++) {
            int k = kk * 3;
            if (k + 2 < KTAPS) LOAD_TAP(A2, k + 2);
            MMA_TAP(A0, k);
            if (k + 3 < KTAPS) LOAD_TAP(A0, k + 3);
            MMA_TAP(A1, k + 1);
            if (k + 4 < KTAPS) LOAD_TAP(A1, k + 4);
            MMA_TAP(A2, k + 2);
        }

        // Epilogue: streaming stores (bias already in acc)
        #pragma unroll
        for (int mt = 0; mt < 2; mt++) {
            #pragma unroll
            for (int half = 0; half < 2; half++) {
                int r = i0 + mb + mt * 16 + nrow + half * 8;
                if (r < n) {
                    float* po = out + (size_t)r * COUT + 2 * q;
                    #pragma unroll
                    for (int t = 0; t < 4; t++) {
                        float2 v;
                        v.x = acc[mt][t][half * 2 + 0];
                        v.y = acc[mt][t][half * 2 + 1];
                        __stcs((float2*)(po + t * 8), v);
                    }
                }
            }
        }
    }
}

// ---------------- Launch ----------------
extern "C" void kernel_launch(void* const* d_in, const int* in_sizes, int n_in,
                              void* d_out, int out_size) {
    const float* x    = (const float*)d_in[0];       // [N, 32] f32
    const float* w    = (const float*)d_in[1];       // [27, 32, 32] f32
    const float* bias = (const float*)d_in[2];       // [32] f32
    const void*  nbr  = d_in[3];                     // [N, 27] int32 OR int64 (detected)
    float*       out  = (float*)d_out;               // [N, 32] f32

    const int n = in_sizes[0] / CIN;
    const int ntiles = (n + MBLOCK - 1) / MBLOCK;

    int nsm = 148;
    cudaDeviceGetAttribute(&nsm, cudaDevAttrMultiProcessorCount, 0);
    int grid = 2 * nsm;
    if (grid > ntiles) grid = ntiles;

    cudaFuncSetAttribute(conv_main_kernel,
                         cudaFuncAttributeMaxDynamicSharedMemorySize, SMEM_BYTES);

    detect_nbr_kernel<<<1, 256>>>((const int*)nbr);
    {
        long long total = (long long)n * 16;
        int blocks = (int)((total + NTHREADS - 1) / NTHREADS);
        convert_x_kernel<<<blocks, NTHREADS>>>(x, n);
    }
    {
        int total = KTAPS * COUT * CIN;
        convert_w_kernel<<<(total + NTHREADS - 1) / NTHREADS, NTHREADS>>>(w);
    }
    conv_main_kernel<<<grid, NTHREADS, SMEM_BYTES>>>(nbr, bias, out, n, ntiles);
}